// round 2
// baseline (speedup 1.0000x reference)
#include <cuda_runtime.h>
#include <cuda_bf16.h>
#include <math.h>

// Problem constants (fixed shapes from setup_inputs)
#define ME   128          // max electrons (n_e)
#define MN   128          // max nuclei
#define NDET 32
#define NO   (NDET*ME)    // 4096 orbitals per spin
#define LOG2E 1.4426950408889634f

// Scratch (static device globals — no runtime allocation)
__device__ float g_feats[MN * 4];
__device__ float g_zl[2 * NO * MN];     // -|zeta|*log2e, layout [s][o][n]
__device__ float g_pi[2 * NO * MN];     // nuclear weights, layout [s][o][n]
__device__ float g_dist[2 * ME * MN];   // masked distances, layout [s][e][n]
__device__ unsigned char g_em[2][ME];   // normalized electron masks (up, down)
__device__ unsigned char g_nm[MN];      // normalized nuclear mask

__device__ __forceinline__ float ex2(float x) {
    float y;
    asm("ex2.approx.ftz.f32 %0, %1;" : "=f"(y) : "f"(x));
    return y;
}

// ---------------------------------------------------------------------------
// Kernel 0: mask normalization. The harness may materialize the bool masks as
// uint8, int32, or float32; sniff the encoding from the first 128 bytes (safe
// to read for every candidate dtype) and write canonical uint8.
// ---------------------------------------------------------------------------
__device__ void norm_mask(const unsigned char* p, unsigned char* out, int tid) {
    __shared__ unsigned int ws[32];
    if (tid < 32) ws[tid] = ((const unsigned int*)p)[tid];
    __syncthreads();
    bool anyFloat = false, allSmall = true, anyOne = false, anyNZ = false;
    #pragma unroll
    for (int i = 0; i < 32; i++) {
        unsigned int w = ws[i];
        anyFloat |= (w == 0x3F800000u) || ((w & 0x7F800000u) >= 0x38000000u && (w & 0x7F800000u) <= 0x47000000u);
        anyNZ    |= (w != 0u);
        allSmall &= (w <= 1u);
        anyOne   |= (w == 1u);
    }
    int mode;                 // 0=uint8, 1=int32, 2=float32, 3=all-false
    if (!anyNZ)               mode = 3;
    else if (anyFloat)        mode = 2;
    else if (allSmall && anyOne) mode = 1;
    else                      mode = 0;
    __syncthreads();
    if (tid < 128) {
        unsigned char v;
        if      (mode == 2) v = (((const float*)p)[tid] != 0.0f);
        else if (mode == 1) v = (((const int*)p)[tid] != 0);
        else if (mode == 3) v = 0;
        else                v = (p[tid] != 0);
        out[tid] = v;
    }
    __syncthreads();
}

__global__ void k_mask(const unsigned char* um, const unsigned char* dm,
                       const unsigned char* nm) {
    int t = threadIdx.x;  // 128 threads
    norm_mask(um, g_em[0], t);
    norm_mask(dm, g_em[1], t);
    norm_mask(nm, g_nm,    t);
}

// ---------------------------------------------------------------------------
// Kernel 1: nuclear features (masked mean-centering + charge)  [1 block]
// ---------------------------------------------------------------------------
__global__ void k_feats(const float* __restrict__ nc,
                        const float* __restrict__ q) {
    __shared__ float rx[MN], ry[MN], rz[MN], rc[MN];
    __shared__ float mean[3];
    int t = threadIdx.x;  // 128 threads
    float m = g_nm[t] ? 1.0f : 0.0f;
    float x = nc[3*t+0], y = nc[3*t+1], z = nc[3*t+2];
    rx[t] = x * m; ry[t] = y * m; rz[t] = z * m; rc[t] = m;
    __syncthreads();
    for (int off = 64; off > 0; off >>= 1) {
        if (t < off) {
            rx[t] += rx[t+off]; ry[t] += ry[t+off];
            rz[t] += rz[t+off]; rc[t] += rc[t+off];
        }
        __syncthreads();
    }
    if (t == 0) {
        float cnt = fmaxf(rc[0], 1.0f);
        mean[0] = rx[0] / cnt; mean[1] = ry[0] / cnt; mean[2] = rz[0] / cnt;
    }
    __syncthreads();
    g_feats[4*t+0] = q[t] * m;
    g_feats[4*t+1] = (x - mean[0]) * m;
    g_feats[4*t+2] = (y - mean[1]) * m;
    g_feats[4*t+3] = (z - mean[2]) * m;
}

// ---------------------------------------------------------------------------
// Kernel 2: per-(s,o,n) zeta/pi from the K=4 linear maps; pre-fold -|.|*log2e
// ---------------------------------------------------------------------------
__global__ void k_wts(const float* __restrict__ Wpu, const float* __restrict__ Wzu,
                      const float* __restrict__ Wpd, const float* __restrict__ Wzd) {
    int t = blockIdx.x * blockDim.x + threadIdx.x;   // 2*4096*128 = 2^20 threads
    int n = t & (MN - 1);
    int o = (t >> 7) & (NO - 1);
    int s = t >> 19;
    const float* Wp = s ? Wpd : Wpu;   // zeta (exponent factor) comes from W_pi
    const float* Wz = s ? Wzd : Wzu;   // pi (nuclear weight)   comes from W_zeta
    float f0 = g_feats[4*n+0], f1 = g_feats[4*n+1];
    float f2 = g_feats[4*n+2], f3 = g_feats[4*n+3];
    float zeta = f0*Wp[o] + f1*Wp[NO+o] + f2*Wp[2*NO+o] + f3*Wp[3*NO+o];
    float pi   = f0*Wz[o] + f1*Wz[NO+o] + f2*Wz[2*NO+o] + f3*Wz[3*NO+o];
    g_zl[t] = -fabsf(zeta) * LOG2E;
    g_pi[t] = pi;
}

// ---------------------------------------------------------------------------
// Kernel 3: masked electron-nucleus distances
// ---------------------------------------------------------------------------
__global__ void k_dist(const float* __restrict__ up, const float* __restrict__ dn,
                       const float* __restrict__ nc) {
    int t = blockIdx.x * blockDim.x + threadIdx.x;   // 2*128*128 = 32768
    int n = t & (MN - 1);
    int e = (t >> 7) & (ME - 1);
    int s = t >> 14;
    const float* ec = s ? dn : up;
    float dx = ec[3*e+0] - nc[3*n+0];
    float dy = ec[3*e+1] - nc[3*n+1];
    float dz = ec[3*e+2] - nc[3*n+2];
    float d2 = dx*dx + dy*dy + dz*dz;
    bool ok = (g_em[s][e] != 0) && (g_nm[n] != 0);
    g_dist[t] = sqrtf(ok ? d2 : 1.0f);
}

// ---------------------------------------------------------------------------
// Main kernel: orb[e,o] = sum_n pi[o,n] * exp2(dist[e,n] * zl[o,n])
// Block = (spin, 16-orbital tile). 256 threads, each owns 4e x 2o cells.
// smem rows padded to 132 words -> all LDS.128 patterns bank-conflict-free.
// NOTE: masked (e,n) pairs must contribute 0 (reference zeroes expo), but for
// masked nuclei pi==0 already (feats *= nuc_mask), and masked-electron rows
// are overwritten by the eye substitution in the epilogue — so no extra work.
// ---------------------------------------------------------------------------
#define ROWP 132
#define SMEM_FLOATS (ME*ROWP + 2*16*ROWP)   // 16896 + 4224 = 21120

__global__ void __launch_bounds__(256) k_main(float* __restrict__ out) {
    extern __shared__ float smem[];
    float* sd  = smem;                 // [128][132] dist
    float* szl = smem + ME * ROWP;     // [16][132]
    float* spi = szl + 16 * ROWP;      // [16][132]

    int bx  = blockIdx.x;
    int s   = bx >> 8;                 // 256 o-tiles per spin
    int ot  = bx & 255;
    int tid = threadIdx.x;

    // Fill dist tile (whole [128 e][128 n] for this spin)
    const float4* gd = (const float4*)(g_dist + s * ME * MN);
    #pragma unroll
    for (int i = tid; i < ME * 32; i += 256) {
        int e = i >> 5, c = i & 31;
        *(float4*)(sd + e * ROWP + c * 4) = gd[i];
    }
    // Fill zl/pi for this 16-orbital tile
    const float4* gz = (const float4*)(g_zl + (s * NO + ot * 16) * MN);
    const float4* gp = (const float4*)(g_pi + (s * NO + ot * 16) * MN);
    #pragma unroll
    for (int i = tid; i < 16 * 32; i += 256) {
        int o = i >> 5, c = i & 31;
        *(float4*)(szl + o * ROWP + c * 4) = gz[i];
        *(float4*)(spi + o * ROWP + c * 4) = gp[i];
    }
    __syncthreads();

    int eg = tid >> 3;       // 0..31 ; thread's electrons: eg + 32*ei
    int og = tid & 7;        // 0..7  ; thread's orbitals:  og + 8*oj

    float acc[4][2];
    #pragma unroll
    for (int ei = 0; ei < 4; ei++)
        #pragma unroll
        for (int oj = 0; oj < 2; oj++) acc[ei][oj] = 0.0f;

    const float* sd0 = sd  + eg * ROWP;
    const float* z0  = szl + og * ROWP;
    const float* p0  = spi + og * ROWP;

    #pragma unroll 4
    for (int c = 0; c < 32; c++) {
        float4 d0 = *(const float4*)(sd0 +   0 * ROWP + c * 4);
        float4 d1 = *(const float4*)(sd0 +  32 * ROWP + c * 4);
        float4 d2 = *(const float4*)(sd0 +  64 * ROWP + c * 4);
        float4 d3 = *(const float4*)(sd0 +  96 * ROWP + c * 4);
        #pragma unroll
        for (int oj = 0; oj < 2; oj++) {
            float4 z = *(const float4*)(z0 + oj * 8 * ROWP + c * 4);
            float4 p = *(const float4*)(p0 + oj * 8 * ROWP + c * 4);
            float4 dd[4] = {d0, d1, d2, d3};
            #pragma unroll
            for (int ei = 0; ei < 4; ei++) {
                float a = acc[ei][oj];
                a = fmaf(p.x, ex2(dd[ei].x * z.x), a);
                a = fmaf(p.y, ex2(dd[ei].y * z.y), a);
                a = fmaf(p.z, ex2(dd[ei].z * z.z), a);
                a = fmaf(p.w, ex2(dd[ei].w * z.w), a);
                acc[ei][oj] = a;
            }
        }
    }

    // Epilogue: out[s][d][e][m], o = d*128 + m ; eye-substitution on e-mask
    int o_base = ot * 16;
    #pragma unroll
    for (int ei = 0; ei < 4; ei++) {
        int e = eg + 32 * ei;
        bool eok = (g_em[s][e] != 0);
        #pragma unroll
        for (int oj = 0; oj < 2; oj++) {
            int o = o_base + og + 8 * oj;
            int d = o >> 7, m = o & 127;
            float v = (eok && (g_em[s][m] != 0)) ? acc[ei][oj]
                                                 : (e == m ? 1.0f : 0.0f);
            out[(((s << 5) + d) << 14) + (e << 7) + m] = v;
        }
    }
}

// ---------------------------------------------------------------------------
extern "C" void kernel_launch(void* const* d_in, const int* in_sizes, int n_in,
                              void* d_out, int out_size) {
    const float* up  = (const float*)d_in[0];
    const float* dn  = (const float*)d_in[1];
    const float* nc  = (const float*)d_in[2];
    const float* q   = (const float*)d_in[3];
    const float* Wpu = (const float*)d_in[4];
    const float* Wzu = (const float*)d_in[5];
    const float* Wpd = (const float*)d_in[6];
    const float* Wzd = (const float*)d_in[7];
    const unsigned char* um = (const unsigned char*)d_in[8];
    const unsigned char* dm = (const unsigned char*)d_in[9];
    const unsigned char* nm = (const unsigned char*)d_in[10];
    float* out = (float*)d_out;

    k_mask<<<1, 128>>>(um, dm, nm);
    k_feats<<<1, 128>>>(nc, q);
    k_wts<<<(2 * NO * MN) / 256, 256>>>(Wpu, Wzu, Wpd, Wzd);
    k_dist<<<(2 * ME * MN) / 256, 256>>>(up, dn, nc);

    cudaFuncSetAttribute(k_main, cudaFuncAttributeMaxDynamicSharedMemorySize,
                         SMEM_FLOATS * sizeof(float));
    k_main<<<512, 256, SMEM_FLOATS * sizeof(float)>>>(out);
}

// round 3
// speedup vs baseline: 1.0584x; 1.0584x over previous
#include <cuda_runtime.h>
#include <cuda_bf16.h>
#include <math.h>

// Problem constants (fixed shapes from setup_inputs)
#define ME   128          // max electrons (n_e)
#define MN   128          // max nuclei
#define NDET 32
#define NO   (NDET*ME)    // 4096 orbitals per spin
#define LOG2E 1.4426950408889634f

#define ROWP 132          // padded row (floats) -> conflict-free LDS.128
// smem carve (floats):
//   sd   [128*132] dist tile (also reused as reduction scratch pre-fill)
//   szl  [16*132]  -|zeta|*log2e tile
//   spi  [16*132]  pi tile
//   sfe  [128*4]   nuclear feats
//   snc  [128*4]   nuclear coords (xyz + pad)
//   sec  [128*4]   electron coords (xyz + pad)
#define OFF_SZL (ME*ROWP)
#define OFF_SPI (OFF_SZL + 16*ROWP)
#define OFF_SFE (OFF_SPI + 16*ROWP)
#define OFF_SNC (OFF_SFE + 128*4)
#define OFF_SEC (OFF_SNC + 128*4)
#define SMEM_FLOATS (OFF_SEC + 128*4)   // 22656 floats = 90624 B

__device__ __forceinline__ float ex2(float x) {
    float y;
    asm("ex2.approx.ftz.f32 %0, %1;" : "=f"(y) : "f"(x));
    return y;
}
__device__ __forceinline__ float fsqrt_approx(float x) {
    float y;
    asm("sqrt.approx.ftz.f32 %0, %1;" : "=f"(y) : "f"(x));
    return y;
}

// Mask normalization: harness may materialize bool as uint8/int32/float32.
// Sniff encoding from first 128 bytes (safe for every candidate dtype).
// 256-thread collective; writes canonical uint8 into smem `out[128]`.
__device__ void norm_mask256(const unsigned char* __restrict__ p,
                             unsigned char* out, unsigned int* ws, int tid) {
    if (tid < 32) ws[tid] = ((const unsigned int*)p)[tid];
    __syncthreads();
    bool anyFloat = false, allSmall = true, anyNZ = false;
    #pragma unroll
    for (int i = 0; i < 32; i++) {
        unsigned int w = ws[i];
        anyFloat |= (w == 0x3F800000u) ||
                    ((w & 0x7F800000u) >= 0x38000000u && (w & 0x7F800000u) <= 0x47000000u);
        anyNZ    |= (w != 0u);
        allSmall &= (w <= 1u);
    }
    int mode;                 // 0=uint8, 1=int32, 2=float32, 3=all-false
    if (!anyNZ)            mode = 3;
    else if (anyFloat)     mode = 2;
    else if (allSmall)     mode = 1;
    else                   mode = 0;
    if (tid < 128) {
        unsigned char v;
        if      (mode == 2) v = (((const float*)p)[tid] != 0.0f);
        else if (mode == 1) v = (((const int*)p)[tid] != 0);
        else if (mode == 3) v = 0;
        else                v = (p[tid] != 0);
        out[tid] = v;
    }
    __syncthreads();
}

// ---------------------------------------------------------------------------
// Single fused kernel.
// Block = (spin, 16-orbital tile): grid 512, 256 threads, ~90.6KB smem (occ 2).
// Prologue (per block, redundant but cheap): masks -> feats -> dist tile ->
// zl/pi tile. Main loop: orb[e,o] = sum_n pi[o,n] * exp2(dist[e,n]*zl[o,n]).
// ---------------------------------------------------------------------------
__global__ void __launch_bounds__(256) k_fused(
        const float* __restrict__ up, const float* __restrict__ dn,
        const float* __restrict__ nc, const float* __restrict__ q,
        const float* __restrict__ Wpu, const float* __restrict__ Wzu,
        const float* __restrict__ Wpd, const float* __restrict__ Wzd,
        const unsigned char* __restrict__ um, const unsigned char* __restrict__ dm,
        const unsigned char* __restrict__ nm, float* __restrict__ out) {
    extern __shared__ float smem[];
    float* sd  = smem;
    float* szl = smem + OFF_SZL;
    float* spi = smem + OFF_SPI;
    float* sfe = smem + OFF_SFE;
    float* snc = smem + OFF_SNC;
    float* sec = smem + OFF_SEC;
    __shared__ unsigned int ws[32];
    __shared__ unsigned char sem[128];   // this spin's electron mask
    __shared__ unsigned char snm[128];   // nuclear mask
    __shared__ float smean[3];

    int bx  = blockIdx.x;
    int s   = bx >> 8;                 // spin
    int ot  = bx & 255;                // 16-orbital tile index
    int tid = threadIdx.x;

    const float* ec = s ? dn : up;
    const float* Wp = s ? Wpd : Wpu;   // zeta comes from W_pi
    const float* Wz = s ? Wzd : Wzu;   // pi   comes from W_zeta

    // --- masks ---
    norm_mask256(s ? dm : um, sem, ws, tid);
    norm_mask256(nm,          snm, ws, tid);

    // --- stage coords; masked mean reduction (scratch lives in sd) ---
    float* rx = sd; float* ry = sd + 128; float* rz = sd + 256; float* rc = sd + 384;
    if (tid < 128) {
        float m = snm[tid] ? 1.0f : 0.0f;
        float x = nc[3*tid+0], y = nc[3*tid+1], z = nc[3*tid+2];
        snc[4*tid+0] = x; snc[4*tid+1] = y; snc[4*tid+2] = z; snc[4*tid+3] = m;
        sec[4*tid+0] = ec[3*tid+0]; sec[4*tid+1] = ec[3*tid+1]; sec[4*tid+2] = ec[3*tid+2];
        rx[tid] = x * m; ry[tid] = y * m; rz[tid] = z * m; rc[tid] = m;
    }
    __syncthreads();
    #pragma unroll
    for (int off = 64; off > 0; off >>= 1) {
        if (tid < off) {
            rx[tid] += rx[tid+off]; ry[tid] += ry[tid+off];
            rz[tid] += rz[tid+off]; rc[tid] += rc[tid+off];
        }
        __syncthreads();
    }
    if (tid == 0) {
        float cnt = fmaxf(rc[0], 1.0f);
        smean[0] = rx[0] / cnt; smean[1] = ry[0] / cnt; smean[2] = rz[0] / cnt;
    }
    __syncthreads();
    // --- feats (after scratch consumed) ---
    if (tid < 128) {
        float m = snc[4*tid+3];
        sfe[4*tid+0] = q[tid] * m;
        sfe[4*tid+1] = (snc[4*tid+0] - smean[0]) * m;
        sfe[4*tid+2] = (snc[4*tid+1] - smean[1]) * m;
        sfe[4*tid+3] = (snc[4*tid+2] - smean[2]) * m;
    }
    __syncthreads();

    // --- dist tile [128 e][128 n] (no masking needed: masked-n => pi=zeta=0;
    //     masked-e rows are overwritten by the eye epilogue) ---
    #pragma unroll
    for (int i = tid; i < ME * MN; i += 256) {
        int e = i >> 7, n = i & 127;
        float dx = sec[4*e+0] - snc[4*n+0];
        float dy = sec[4*e+1] - snc[4*n+1];
        float dz = sec[4*e+2] - snc[4*n+2];
        sd[e * ROWP + n] = fsqrt_approx(fmaf(dx, dx, fmaf(dy, dy, dz*dz)));
    }

    // --- zl/pi tile for this block's 16 orbitals ---
    int o_base = ot * 16;
    #pragma unroll
    for (int j = tid; j < 16 * MN; j += 256) {
        int ol = j >> 7, n = j & 127;
        int o  = o_base + ol;
        float f0 = sfe[4*n+0], f1 = sfe[4*n+1], f2 = sfe[4*n+2], f3 = sfe[4*n+3];
        float zeta = fmaf(f0, Wp[o], fmaf(f1, Wp[NO+o], fmaf(f2, Wp[2*NO+o], f3 * Wp[3*NO+o])));
        float pi   = fmaf(f0, Wz[o], fmaf(f1, Wz[NO+o], fmaf(f2, Wz[2*NO+o], f3 * Wz[3*NO+o])));
        szl[ol * ROWP + n] = -fabsf(zeta) * LOG2E;
        spi[ol * ROWP + n] = pi;
    }
    __syncthreads();

    // --- main loop: each thread owns 4e x 2o cells ---
    int eg = tid >> 3;       // 0..31 ; electrons: eg + 32*ei
    int og = tid & 7;        // 0..7  ; orbitals:  og + 8*oj

    float acc[4][2];
    #pragma unroll
    for (int ei = 0; ei < 4; ei++)
        #pragma unroll
        for (int oj = 0; oj < 2; oj++) acc[ei][oj] = 0.0f;

    const float* sd0 = sd  + eg * ROWP;
    const float* z0  = szl + og * ROWP;
    const float* p0  = spi + og * ROWP;

    #pragma unroll 4
    for (int c = 0; c < 32; c++) {
        float4 d0 = *(const float4*)(sd0 +   0 * ROWP + c * 4);
        float4 d1 = *(const float4*)(sd0 +  32 * ROWP + c * 4);
        float4 d2 = *(const float4*)(sd0 +  64 * ROWP + c * 4);
        float4 d3 = *(const float4*)(sd0 +  96 * ROWP + c * 4);
        #pragma unroll
        for (int oj = 0; oj < 2; oj++) {
            float4 z = *(const float4*)(z0 + oj * 8 * ROWP + c * 4);
            float4 p = *(const float4*)(p0 + oj * 8 * ROWP + c * 4);
            float4 dd[4] = {d0, d1, d2, d3};
            #pragma unroll
            for (int ei = 0; ei < 4; ei++) {
                float a = acc[ei][oj];
                a = fmaf(p.x, ex2(dd[ei].x * z.x), a);
                a = fmaf(p.y, ex2(dd[ei].y * z.y), a);
                a = fmaf(p.z, ex2(dd[ei].z * z.z), a);
                a = fmaf(p.w, ex2(dd[ei].w * z.w), a);
                acc[ei][oj] = a;
            }
        }
    }

    // --- epilogue: out[s][d][e][m], o = d*128 + m ; eye substitution on e-mask ---
    #pragma unroll
    for (int ei = 0; ei < 4; ei++) {
        int e = eg + 32 * ei;
        bool eok = (sem[e] != 0);
        #pragma unroll
        for (int oj = 0; oj < 2; oj++) {
            int o = o_base + og + 8 * oj;
            int d = o >> 7, m = o & 127;
            float v = (eok && (sem[m] != 0)) ? acc[ei][oj]
                                             : (e == m ? 1.0f : 0.0f);
            out[(((s << 5) + d) << 14) + (e << 7) + m] = v;
        }
    }
}

// ---------------------------------------------------------------------------
extern "C" void kernel_launch(void* const* d_in, const int* in_sizes, int n_in,
                              void* d_out, int out_size) {
    const float* up  = (const float*)d_in[0];
    const float* dn  = (const float*)d_in[1];
    const float* nc  = (const float*)d_in[2];
    const float* q   = (const float*)d_in[3];
    const float* Wpu = (const float*)d_in[4];
    const float* Wzu = (const float*)d_in[5];
    const float* Wpd = (const float*)d_in[6];
    const float* Wzd = (const float*)d_in[7];
    const unsigned char* um = (const unsigned char*)d_in[8];
    const unsigned char* dm = (const unsigned char*)d_in[9];
    const unsigned char* nm = (const unsigned char*)d_in[10];
    float* out = (float*)d_out;

    cudaFuncSetAttribute(k_fused, cudaFuncAttributeMaxDynamicSharedMemorySize,
                         SMEM_FLOATS * sizeof(float));
    k_fused<<<512, 256, SMEM_FLOATS * sizeof(float)>>>(
        up, dn, nc, q, Wpu, Wzu, Wpd, Wzd, um, dm, nm, out);
}

// round 4
// speedup vs baseline: 1.2551x; 1.1858x over previous
#include <cuda_runtime.h>
#include <cuda_bf16.h>
#include <math.h>

// Problem constants (fixed shapes from setup_inputs)
#define ME   128          // max electrons (n_e)
#define MN   128          // max nuclei
#define NDET 32
#define NO   (NDET*ME)    // 4096 orbitals per spin
#define LOG2E 1.4426950408889634f
#define NBLK 296          // 2 blocks/SM * 148 SMs -> exactly one wave
#define BPS  148          // blocks per spin

#define ROWP 132          // padded row (floats): stride = 4 banks -> conflict-free
#define OFF_SZL (ME*ROWP)
#define OFF_SPI (OFF_SZL + 16*ROWP)
#define OFF_SFE (OFF_SPI + 16*ROWP)
#define OFF_SNC (OFF_SFE + 128*4)
#define OFF_SEC (OFF_SNC + 128*4)
#define SMEM_FLOATS (OFF_SEC + 128*4)   // 22656 floats = 90624 B -> 2 blocks/SM

__device__ __forceinline__ float ex2(float x) {
    float y; asm("ex2.approx.ftz.f32 %0, %1;" : "=f"(y) : "f"(x)); return y;
}
__device__ __forceinline__ float fsqrt_approx(float x) {
    float y; asm("sqrt.approx.ftz.f32 %0, %1;" : "=f"(y) : "f"(x)); return y;
}

// Mask normalization: harness may materialize bool as uint8/int32/float32.
__device__ void norm_mask256(const unsigned char* __restrict__ p,
                             unsigned char* out, unsigned int* ws, int tid) {
    if (tid < 32) ws[tid] = ((const unsigned int*)p)[tid];
    __syncthreads();
    bool anyFloat = false, allSmall = true, anyNZ = false;
    #pragma unroll
    for (int i = 0; i < 32; i++) {
        unsigned int w = ws[i];
        anyFloat |= (w == 0x3F800000u) ||
                    ((w & 0x7F800000u) >= 0x38000000u && (w & 0x7F800000u) <= 0x47000000u);
        anyNZ    |= (w != 0u);
        allSmall &= (w <= 1u);
    }
    int mode;
    if (!anyNZ)        mode = 3;
    else if (anyFloat) mode = 2;
    else if (allSmall) mode = 1;
    else               mode = 0;
    if (tid < 128) {
        unsigned char v;
        if      (mode == 2) v = (((const float*)p)[tid] != 0.0f);
        else if (mode == 1) v = (((const int*)p)[tid] != 0);
        else if (mode == 3) v = 0;
        else                v = (p[tid] != 0);
        out[tid] = v;
    }
    __syncthreads();
}

__global__ void __launch_bounds__(256) k_fused(
        const float* __restrict__ up, const float* __restrict__ dn,
        const float* __restrict__ nc, const float* __restrict__ q,
        const float* __restrict__ Wpu, const float* __restrict__ Wzu,
        const float* __restrict__ Wpd, const float* __restrict__ Wzd,
        const unsigned char* __restrict__ um, const unsigned char* __restrict__ dm,
        const unsigned char* __restrict__ nm, float* __restrict__ out) {
    extern __shared__ float smem[];
    float* sd  = smem;
    float* szl = smem + OFF_SZL;
    float* spi = smem + OFF_SPI;
    float* sfe = smem + OFF_SFE;
    float* snc = smem + OFF_SNC;
    float* sec = smem + OFF_SEC;
    __shared__ unsigned int ws[32];
    __shared__ unsigned char sem[128];
    __shared__ unsigned char snm[128];
    __shared__ float smean[3];

    int bx  = blockIdx.x;
    int s   = (bx >= BPS) ? 1 : 0;
    int bl  = bx - s * BPS;
    int tid = threadIdx.x;

    // Ragged contiguous orbital range: 27 or 28 orbitals per block.
    int o_start = (bl * NO) / BPS;
    int o_end   = ((bl + 1) * NO) / BPS;

    const float* ec = s ? dn : up;
    const float* Wp = s ? Wpd : Wpu;   // zeta comes from W_pi
    const float* Wz = s ? Wzd : Wzu;   // pi   comes from W_zeta

    // --- masks ---
    norm_mask256(s ? dm : um, sem, ws, tid);
    norm_mask256(nm,          snm, ws, tid);

    // --- coords; masked mean reduction (scratch in sd) ---
    float* rx = sd; float* ry = sd + 128; float* rz = sd + 256; float* rc = sd + 384;
    if (tid < 128) {
        float m = snm[tid] ? 1.0f : 0.0f;
        float x = nc[3*tid+0], y = nc[3*tid+1], z = nc[3*tid+2];
        snc[4*tid+0] = x; snc[4*tid+1] = y; snc[4*tid+2] = z; snc[4*tid+3] = m;
        sec[4*tid+0] = ec[3*tid+0]; sec[4*tid+1] = ec[3*tid+1]; sec[4*tid+2] = ec[3*tid+2];
        rx[tid] = x * m; ry[tid] = y * m; rz[tid] = z * m; rc[tid] = m;
    }
    __syncthreads();
    #pragma unroll
    for (int off = 64; off > 0; off >>= 1) {
        if (tid < off) {
            rx[tid] += rx[tid+off]; ry[tid] += ry[tid+off];
            rz[tid] += rz[tid+off]; rc[tid] += rc[tid+off];
        }
        __syncthreads();
    }
    if (tid == 0) {
        float cnt = fmaxf(rc[0], 1.0f);
        smean[0] = rx[0] / cnt; smean[1] = ry[0] / cnt; smean[2] = rz[0] / cnt;
    }
    __syncthreads();
    if (tid < 128) {
        float m = snc[4*tid+3];
        sfe[4*tid+0] = q[tid] * m;
        sfe[4*tid+1] = (snc[4*tid+0] - smean[0]) * m;
        sfe[4*tid+2] = (snc[4*tid+1] - smean[1]) * m;
        sfe[4*tid+3] = (snc[4*tid+2] - smean[2]) * m;
    }
    __syncthreads();

    // --- dist tile [128 e][128 n] (masking unnecessary: masked-n => pi=zeta=0;
    //     masked-e rows overwritten by eye epilogue) ---
    #pragma unroll
    for (int i = tid; i < ME * MN; i += 256) {
        int e = i >> 7, n = i & 127;
        float dx = sec[4*e+0] - snc[4*n+0];
        float dy = sec[4*e+1] - snc[4*n+1];
        float dz = sec[4*e+2] - snc[4*n+2];
        sd[e * ROWP + n] = fsqrt_approx(fmaf(dx, dx, fmaf(dy, dy, dz*dz)));
    }

    // =============== chunk 0: 16 orbitals at o_start (always full) ===========
    #pragma unroll
    for (int j = tid; j < 16 * MN; j += 256) {
        int ol = j >> 7, n = j & 127;
        int o  = o_start + ol;
        float f0 = sfe[4*n+0], f1 = sfe[4*n+1], f2 = sfe[4*n+2], f3 = sfe[4*n+3];
        float zeta = fmaf(f0, Wp[o], fmaf(f1, Wp[NO+o], fmaf(f2, Wp[2*NO+o], f3 * Wp[3*NO+o])));
        float pi   = fmaf(f0, Wz[o], fmaf(f1, Wz[NO+o], fmaf(f2, Wz[2*NO+o], f3 * Wz[3*NO+o])));
        szl[ol * ROWP + n] = -fabsf(zeta) * LOG2E;
        spi[ol * ROWP + n] = pi;
    }
    __syncthreads();

    {   // map A: eg = tid>>3 (0..31) -> e = eg+32*ei ; og = tid&7 -> o = og+8*oj
        int eg = tid >> 3, og = tid & 7;
        float acc[4][2];
        #pragma unroll
        for (int ei = 0; ei < 4; ei++)
            #pragma unroll
            for (int oj = 0; oj < 2; oj++) acc[ei][oj] = 0.0f;
        const float* sd0 = sd  + eg * ROWP;
        const float* z0  = szl + og * ROWP;
        const float* p0  = spi + og * ROWP;
        #pragma unroll 4
        for (int c = 0; c < 32; c++) {
            float4 d0 = *(const float4*)(sd0 +  0 * ROWP + c * 4);
            float4 d1 = *(const float4*)(sd0 + 32 * ROWP + c * 4);
            float4 d2 = *(const float4*)(sd0 + 64 * ROWP + c * 4);
            float4 d3 = *(const float4*)(sd0 + 96 * ROWP + c * 4);
            #pragma unroll
            for (int oj = 0; oj < 2; oj++) {
                float4 z = *(const float4*)(z0 + oj * 8 * ROWP + c * 4);
                float4 p = *(const float4*)(p0 + oj * 8 * ROWP + c * 4);
                float4 dd[4] = {d0, d1, d2, d3};
                #pragma unroll
                for (int ei = 0; ei < 4; ei++) {
                    float a = acc[ei][oj];
                    a = fmaf(p.x, ex2(dd[ei].x * z.x), a);
                    a = fmaf(p.y, ex2(dd[ei].y * z.y), a);
                    a = fmaf(p.z, ex2(dd[ei].z * z.z), a);
                    a = fmaf(p.w, ex2(dd[ei].w * z.w), a);
                    acc[ei][oj] = a;
                }
            }
        }
        #pragma unroll
        for (int ei = 0; ei < 4; ei++) {
            int e = eg + 32 * ei;
            bool eok = (sem[e] != 0);
            #pragma unroll
            for (int oj = 0; oj < 2; oj++) {
                int o = o_start + og + 8 * oj;
                int d = o >> 7, m = o & 127;
                float v = (eok && (sem[m] != 0)) ? acc[ei][oj]
                                                 : (e == m ? 1.0f : 0.0f);
                out[(((s << 5) + d) << 14) + (e << 7) + m] = v;
            }
        }
    }
    __syncthreads();   // before zl/pi reuse

    // =============== chunk 1: up to 12 orbitals at o_start+16 ================
    int cw = o_end - (o_start + 16);   // 11 or 12
    #pragma unroll
    for (int j = tid; j < 12 * MN; j += 256) {
        int ol = j >> 7, n = j & 127;
        int o  = o_start + 16 + ol;
        float zl = 0.0f, pi = 0.0f;
        if (ol < cw) {
            float f0 = sfe[4*n+0], f1 = sfe[4*n+1], f2 = sfe[4*n+2], f3 = sfe[4*n+3];
            float zeta = fmaf(f0, Wp[o], fmaf(f1, Wp[NO+o], fmaf(f2, Wp[2*NO+o], f3 * Wp[3*NO+o])));
            pi   = fmaf(f0, Wz[o], fmaf(f1, Wz[NO+o], fmaf(f2, Wz[2*NO+o], f3 * Wz[3*NO+o])));
            zl   = -fabsf(zeta) * LOG2E;
        }
        szl[ol * ROWP + n] = zl;
        spi[ol * ROWP + n] = pi;
    }
    __syncthreads();

    {   // map B: eg2 = tid>>2 (0..63) -> e = eg2+64*ei ; og2 = tid&3 -> ol = og2+4*oj (oj 0..2)
        int eg2 = tid >> 2, og2 = tid & 3;
        float acc[2][3];
        #pragma unroll
        for (int ei = 0; ei < 2; ei++)
            #pragma unroll
            for (int oj = 0; oj < 3; oj++) acc[ei][oj] = 0.0f;
        const float* sd0 = sd  + eg2 * ROWP;
        const float* z0  = szl + og2 * ROWP;
        const float* p0  = spi + og2 * ROWP;
        #pragma unroll 4
        for (int c = 0; c < 32; c++) {
            float4 d0 = *(const float4*)(sd0 +  0 * ROWP + c * 4);
            float4 d1 = *(const float4*)(sd0 + 64 * ROWP + c * 4);
            #pragma unroll
            for (int oj = 0; oj < 3; oj++) {
                float4 z = *(const float4*)(z0 + oj * 4 * ROWP + c * 4);
                float4 p = *(const float4*)(p0 + oj * 4 * ROWP + c * 4);
                float4 dd[2] = {d0, d1};
                #pragma unroll
                for (int ei = 0; ei < 2; ei++) {
                    float a = acc[ei][oj];
                    a = fmaf(p.x, ex2(dd[ei].x * z.x), a);
                    a = fmaf(p.y, ex2(dd[ei].y * z.y), a);
                    a = fmaf(p.z, ex2(dd[ei].z * z.z), a);
                    a = fmaf(p.w, ex2(dd[ei].w * z.w), a);
                    acc[ei][oj] = a;
                }
            }
        }
        #pragma unroll
        for (int ei = 0; ei < 2; ei++) {
            int e = eg2 + 64 * ei;
            bool eok = (sem[e] != 0);
            #pragma unroll
            for (int oj = 0; oj < 3; oj++) {
                int ol = og2 + 4 * oj;
                if (ol < cw) {
                    int o = o_start + 16 + ol;
                    int d = o >> 7, m = o & 127;
                    float v = (eok && (sem[m] != 0)) ? acc[ei][oj]
                                                     : (e == m ? 1.0f : 0.0f);
                    out[(((s << 5) + d) << 14) + (e << 7) + m] = v;
                }
            }
        }
    }
}

// ---------------------------------------------------------------------------
extern "C" void kernel_launch(void* const* d_in, const int* in_sizes, int n_in,
                              void* d_out, int out_size) {
    const float* up  = (const float*)d_in[0];
    const float* dn  = (const float*)d_in[1];
    const float* nc  = (const float*)d_in[2];
    const float* q   = (const float*)d_in[3];
    const float* Wpu = (const float*)d_in[4];
    const float* Wzu = (const float*)d_in[5];
    const float* Wpd = (const float*)d_in[6];
    const float* Wzd = (const float*)d_in[7];
    const unsigned char* um = (const unsigned char*)d_in[8];
    const unsigned char* dm = (const unsigned char*)d_in[9];
    const unsigned char* nm = (const unsigned char*)d_in[10];
    float* out = (float*)d_out;

    cudaFuncSetAttribute(k_fused, cudaFuncAttributeMaxDynamicSharedMemorySize,
                         SMEM_FLOATS * sizeof(float));
    k_fused<<<NBLK, 256, SMEM_FLOATS * sizeof(float)>>>(
        up, dn, nc, q, Wpu, Wzu, Wpd, Wzd, um, dm, nm, out);
}